// round 6
// baseline (speedup 1.0000x reference)
#include <cuda_runtime.h>
#include <cstdint>

namespace {

constexpr int kB = 64;
constexpr int kN = 8;
constexpr int kV = 128000;
constexpr int kCH = 16;                 // chunks per row
constexpr int kQ4 = kV / kCH / 4;       // float4s per chunk = 2000
constexpr int kTPB = 128;
constexpr int kBonusBlocks = kB * kCH;        // 1024
constexpr int kGridTotal   = 2 * kB * kCH;    // 2048

__device__ float    g_bval[kB * kCH];
__device__ int      g_bidx[kB * kCH];
__device__ float    g_rval[kB * kCH];
__device__ int      g_ridx[kB * kCH];
__device__ unsigned g_ticket;

__device__ __forceinline__ float neg_inf() { return __int_as_float(0xff800000); }

// Force an integer add onto the FMA pipe: mad.lo.u32 with a runtime "1"
// multiplier ptxas cannot const-fold away -> emits IMAD (fma pipe), freeing
// the saturated alu pipe (SHF/LOP3 are pinned there).
__device__ __forceinline__ uint32_t madd(uint32_t a, uint32_t one, uint32_t b) {
  uint32_t r;
  asm("mad.lo.u32 %0, %1, %2, %3;" : "=r"(r) : "r"(a), "r"(one), "r"(b));
  return r;
}

// ---------------- JAX threefry2x32 (exact round structure) -------------------------
__device__ __forceinline__ void tfround(uint32_t& x0, uint32_t& x1, int r, uint32_t one) {
  x0 = madd(x1, one, x0);            // x0 += x1  (IMAD, fma pipe)
  x1 = __funnelshift_l(x1, x1, r);   // SHF (alu)
  x1 ^= x0;                          // LOP3 (alu)
}

// key (k0,k1) is always compile-time constant here; injections become IMADs too.
__device__ __forceinline__ uint2 threefry2x32(uint32_t k0, uint32_t k1,
                                              uint32_t x0, uint32_t x1, uint32_t one) {
  uint32_t k2 = k0 ^ k1 ^ 0x1BD11BDAu;
  x0 = madd(k0, one, x0); x1 = madd(k1, one, x1);
  tfround(x0, x1, 13, one); tfround(x0, x1, 15, one); tfround(x0, x1, 26, one); tfround(x0, x1, 6, one);
  x0 = madd(k1, one, x0); x1 = madd(k2 + 1u, one, x1);
  tfround(x0, x1, 17, one); tfround(x0, x1, 29, one); tfround(x0, x1, 16, one); tfround(x0, x1, 24, one);
  x0 = madd(k2, one, x0); x1 = madd(k0 + 2u, one, x1);
  tfround(x0, x1, 13, one); tfround(x0, x1, 15, one); tfround(x0, x1, 26, one); tfround(x0, x1, 6, one);
  x0 = madd(k0, one, x0); x1 = madd(k1 + 3u, one, x1);
  tfround(x0, x1, 17, one); tfround(x0, x1, 29, one); tfround(x0, x1, 16, one); tfround(x0, x1, 24, one);
  x0 = madd(k1, one, x0); x1 = madd(k2 + 4u, one, x1);
  tfround(x0, x1, 13, one); tfround(x0, x1, 15, one); tfround(x0, x1, 26, one); tfround(x0, x1, 6, one);
  x0 = madd(k2, one, x0); x1 = madd(k0 + 5u, one, x1);
  return make_uint2(x0, x1);
}

__device__ __forceinline__ uint32_t rbits32(uint2 key, uint32_t idx, uint32_t one) {
  uint2 o = threefry2x32(key.x, key.y, 0u, idx, one);
  return o.x ^ o.y;
}

__device__ __forceinline__ float uni01(uint32_t bits) {
  return __uint_as_float((bits >> 9) | 0x3f800000u) - 1.0f;
}

// t = -log(max(u, tiny)), accurate log (relative error matters for u near 1,
// which is exactly where argmax winners live).
__device__ __forceinline__ float tval(uint2 key, uint32_t idx, uint32_t one) {
  float f = uni01(rbits32(key, idx, one));
  float u = fmaxf(f, 1.17549435e-38f);
  return -logf(u);
}

struct BestPair { float v; int i; };

__device__ __forceinline__ void upd(BestPair& b, float v, int i) {
  if (v > b.v) { b.v = v; b.i = i; }
}

// Warp+block argmax (128 threads, tie-break min index), thread 0 holds result.
__device__ __forceinline__ BestPair block_argmax(BestPair best) {
  unsigned full = 0xffffffffu;
#pragma unroll
  for (int off = 16; off > 0; off >>= 1) {
    float ov = __shfl_down_sync(full, best.v, off);
    int   oi = __shfl_down_sync(full, best.i, off);
    if (ov > best.v || (ov == best.v && oi < best.i)) { best.v = ov; best.i = oi; }
  }
  __shared__ float sv[4];
  __shared__ int   si[4];
  int warp = threadIdx.x >> 5;
  int lane = threadIdx.x & 31;
  if (lane == 0) { sv[warp] = best.v; si[warp] = best.i; }
  __syncthreads();
  if (threadIdx.x == 0) {
#pragma unroll
    for (int w = 1; w < 4; w++) {
      if (sv[w] > best.v || (sv[w] == best.v && si[w] < best.i)) {
        best.v = sv[w]; best.i = si[w];
      }
    }
  }
  return best;
}

// accept decision for (b, n)
__device__ __forceinline__ bool accept_bn(int b, int n, const int* __restrict__ tok,
                                          const float* __restrict__ dp,
                                          const float* __restrict__ vp, uint32_t one) {
  uint2 ku = threefry2x32(0u, 1u, 0u, 0u, one);   // split(key(1),3)[0]
  int L = b * kN + n;
  float u = uni01(rbits32(ku, (uint32_t)L, one));
  int t = tok[L];
  t = min(max(t, 0), kV - 1);
  float q = dp[(size_t)L * kV + t];
  float p = vp[((size_t)b * (kN + 1) + n) * kV + t];
  return (u * q < p);
}

// ---------------- Single mega kernel ------------------------------------------------
__global__ void kGumbel(const int* __restrict__ tok, const float* __restrict__ dp,
                        const float* __restrict__ vp, float* __restrict__ out,
                        int out_size, uint32_t one) {
  int blk = blockIdx.x;
  bool is_bonus = blk < kBonusBlocks;
  int rb = is_bonus ? blk : blk - kBonusBlocks;
  int b = rb >> 4;
  int c = rb & (kCH - 1);
  int t = threadIdx.x;

  BestPair best = {neg_inf(), 0x7fffffff};

  if (is_bonus) {
    uint2 kb = threefry2x32(0u, 1u, 0u, 2u, one);  // subkey 2
    const float4* row = (const float4*)(vp + ((size_t)b * (kN + 1) + kN) * kV);
    uint32_t Lbase = (uint32_t)b * (uint32_t)kV;   // gumbel shape (B, V)
#pragma unroll 2
    for (int i = c * kQ4 + t; i < (c + 1) * kQ4; i += kTPB) {
      float4 p4 = row[i];
      int v = 4 * i;
      // maximize (p+eps)/t  ==  argmax log(p+eps) + G  (monotone)
      upd(best, __fdividef(p4.x + 1e-20f, tval(kb, Lbase + v + 0, one)), v + 0);
      upd(best, __fdividef(p4.y + 1e-20f, tval(kb, Lbase + v + 1, one)), v + 1);
      upd(best, __fdividef(p4.z + 1e-20f, tval(kb, Lbase + v + 2, one)), v + 2);
      upd(best, __fdividef(p4.w + 1e-20f, tval(kb, Lbase + v + 3, one)), v + 3);
    }
    best = block_argmax(best);
    if (t == 0) { g_bval[rb] = best.v; g_bidx[rb] = best.i; }
  } else {
    // self-compute em for batch b: lanes 0..7 of warp 0 + ballot
    __shared__ int s_em;
    if (t < 8) {
      bool acc = accept_bn(b, t, tok, dp, vp, one);
      unsigned m = __ballot_sync(0xffu, acc);
      if (t == 0) s_em = __ffs((~m) & 0x1FF) - 1;   // trailing-ones count, 8 if all
    }
    __syncthreads();
    int em = s_em;
    if (em < kN) {
      uint2 kr = threefry2x32(0u, 1u, 0u, 1u, one);  // subkey 1
      const float4* drow = (const float4*)(dp + ((size_t)b * kN + em) * kV);
      const float4* vrow = (const float4*)(vp + ((size_t)b * (kN + 1) + em) * kV);
      uint32_t Lbase = (uint32_t)(b * kN + em) * (uint32_t)kV;  // shape (B, N, V)
#pragma unroll 2
      for (int i = c * kQ4 + t; i < (c + 1) * kQ4; i += kTPB) {
        float4 d4 = drow[i];
        float4 v4 = vrow[i];
        int v = 4 * i;
        upd(best, __fdividef(fmaxf(v4.x - d4.x, 0.0f) + 1e-20f, tval(kr, Lbase + v + 0, one)), v + 0);
        upd(best, __fdividef(fmaxf(v4.y - d4.y, 0.0f) + 1e-20f, tval(kr, Lbase + v + 1, one)), v + 1);
        upd(best, __fdividef(fmaxf(v4.z - d4.z, 0.0f) + 1e-20f, tval(kr, Lbase + v + 2, one)), v + 2);
        upd(best, __fdividef(fmaxf(v4.w - d4.w, 0.0f) + 1e-20f, tval(kr, Lbase + v + 3, one)), v + 3);
      }
      best = block_argmax(best);
      if (t == 0) { g_rval[rb] = best.v; g_ridx[rb] = best.i; }
    }
  }

  // ---- deterministic last-block final assembly -----------------------------------
  __threadfence();
  __shared__ bool amLast;
  if (t == 0) {
    unsigned tk = atomicAdd(&g_ticket, 1u);
    amLast = (tk == (unsigned)(kGridTotal - 1));
  }
  __syncthreads();
  if (!amLast) return;
  if (t == 0) g_ticket = 0;           // reset for next graph replay
  __threadfence();

  int bb = t;
  if (bb < kB) {
    int acc = 0, em = 0;
    bool alive = true;
#pragma unroll
    for (int n = 0; n < kN; n++) {
      bool a = accept_bn(bb, n, tok, dp, vp, one);
      acc += a ? 1 : 0;
      if (alive) { if (a) em++; else alive = false; }
    }
    if (out_size >= kB * (kN + 1) + 2 * kB) {
      out[kB * (kN + 1) + bb] = (float)acc;
      out[kB * (kN + 1) + kB + bb] = (float)em;
    }

    volatile float* bval = g_bval;
    volatile int*   bidx = g_bidx;
    volatile float* rval = g_rval;
    volatile int*   ridx = g_ridx;
    float bv = neg_inf(); int bi = 0x7fffffff;
#pragma unroll
    for (int cc = 0; cc < kCH; cc++) {
      float v = bval[bb * kCH + cc]; int i = bidx[bb * kCH + cc];
      if (v > bv || (v == bv && i < bi)) { bv = v; bi = i; }
    }
    int fin = bi;
    if (em < kN) {
      float rv = neg_inf(); int ri = 0x7fffffff;
#pragma unroll
      for (int cc = 0; cc < kCH; cc++) {
        float v = rval[bb * kCH + cc]; int i = ridx[bb * kCH + cc];
        if (v > rv || (v == rv && i < ri)) { rv = v; ri = i; }
      }
      fin = ri;
    }
#pragma unroll
    for (int pos = 0; pos < kN + 1; pos++) {
      float o;
      if (pos < em)       o = (float)tok[bb * kN + pos];
      else if (pos == em) o = (float)fin;
      else                o = -1.0f;
      out[bb * (kN + 1) + pos] = o;
    }
  }
}

}  // namespace

extern "C" void kernel_launch(void* const* d_in, const int* in_sizes, int n_in,
                              void* d_out, int out_size) {
  const int*   tok = nullptr;
  const float* dp  = nullptr;
  const float* vp  = nullptr;
  for (int i = 0; i < n_in; i++) {
    if (in_sizes[i] == kB * kN)                      tok = (const int*)d_in[i];
    else if (in_sizes[i] == kB * kN * kV)            dp  = (const float*)d_in[i];
    else if (in_sizes[i] == kB * (kN + 1) * kV)      vp  = (const float*)d_in[i];
  }
  float* out = (float*)d_out;

  kGumbel<<<kGridTotal, kTPB>>>(tok, dp, vp, out, out_size, 1u);
}